// round 17
// baseline (speedup 1.0000x reference)
#include <cuda_runtime.h>
#include <cuda_fp16.h>
#include <mma.h>
#include <math_constants.h>
#include <cstdint>

using namespace nvcuda;

#define NROWS 131072
#define D     128
#define NC    512
#define R_TILE 128
#define THREADS 512

#define MARGIN      1e-3f
#define CAND_MARGIN 1.3e-3f

#define AS_LD 136             // halves per row (A tiles, 128-k) -> 272 B, 16B-aligned
#define C1_LD 68              // floats per row (GEMM1 Cbuf, 64 codes) -> 272 B
#define C2_LD 132             // floats per row (epilogue half-buffer) -> 528 B
#define EU_LD 72              // halves per row (eu chunk staging) -> 144 B, 16B-aligned
#define AS_BYTES (R_TILE * AS_LD * 2)        // 34816
#define BS_BYTES (64 * AS_LD * 2)            // 17408
#define REGION_BYTES (2 * R_TILE * EU_LD * 2) // 36864 (>= Cbuf 34816, epi 33792)
#define DYN_BYTES (AS_BYTES + BS_BYTES + REGION_BYTES)   // 89088

// ---------------- global scratch ----------------
__device__ __half g_cf16[NC * D];                  // codebook f16
__device__ __half g_eu  [(size_t)NROWS * NC];      // unnormalized exp (chunk-local max)
__device__ __half g_ab  [(size_t)NROWS * NC];      // ab f16 (tier-2 candidate filter)

__device__ __forceinline__ void cp_async16(void* smem_dst, const void* gsrc) {
    uint32_t d = (uint32_t)__cvta_generic_to_shared(smem_dst);
    asm volatile("cp.async.cg.shared.global [%0], [%1], 16;" :: "r"(d), "l"(gsrc));
}
#define CP_COMMIT() asm volatile("cp.async.commit_group;" ::: "memory")
#define CP_WAIT0()  asm volatile("cp.async.wait_all;" ::: "memory")

// ================= K0: codebook -> f16 =================
__global__ void k0_prep(const float* __restrict__ cb) {
    int i = blockIdx.x * 256 + threadIdx.x;
    if (i < NC * D) g_cf16[i] = __float2half_rn(cb[i]);
}

// ================= K2: everything =================
__global__ void __launch_bounds__(THREADS, 2)
k2_main(const float* __restrict__ x, const float* __restrict__ mask,
        const float* __restrict__ codebook, const float* __restrict__ noise,
        float* __restrict__ out_q, float* __restrict__ out_e, float* __restrict__ out_i) {
    extern __shared__ char dyn[];
    __half* As  = reinterpret_cast<__half*>(dyn);
    __half* Bs  = reinterpret_cast<__half*>(dyn + AS_BYTES);
    char*   region = dyn + AS_BYTES + BS_BYTES;
    float*  Cbuf = reinterpret_cast<float*>(region);
    __half* EUa  = reinterpret_cast<__half*>(region);
    __half* EUb  = reinterpret_cast<__half*>(region + R_TILE * EU_LD * 2);

    __shared__ float s_m1[R_TILE], s_m2[R_TILE];
    __shared__ int   s_i1[R_TILE];
    __shared__ float s_mc[8][R_TILE], s_sc[8][R_TILE], s_ci[8][R_TILE];
    __shared__ int   s_flag[R_TILE];
    __shared__ int   s_cnt;
    __shared__ float s_xw[16][132];     // warp-private xn rows for tier-2

    const int t = threadIdx.x, w = t >> 5, lane = t & 31;
    const int row0 = blockIdx.x * R_TILE;
    const int rg = w >> 2, cg = w & 3;

    if (t < R_TILE) { s_m1[t] = -CUDART_INF_F; s_m2[t] = -CUDART_INF_F; s_i1[t] = 1 << 30; }
    if (t == 0) s_cnt = 0;

    uint32_t* AB32 = reinterpret_cast<uint32_t*>(g_ab);
    uint32_t* EU32 = reinterpret_cast<uint32_t*>(g_eu);

    // preload GEMM1 chunk-0 B (codebook rows 0..63); normalize hides it
    #pragma unroll
    for (int i = 0; i < 2; i++) {
        int idx = t + THREADS * i;
        int r = idx >> 4, c = idx & 15;
        cp_async16(&Bs[r * AS_LD + c * 8], &g_cf16[(size_t)r * 128 + c * 8]);
    }
    CP_COMMIT();

    // ---------------- fused normalize + A staging (R3-verified recipe) ----------------
    for (int hh = 0; hh < 2; hh++) {
        int r = hh * 64 + (t >> 3), q = t & 7;       // 8 threads per row
        const float* xb = x + (size_t)(row0 + r) * D + q * 16;
        float nud = (1.0f - mask[row0 + r]) * 1e-6f;
        float4 xv[4];
        #pragma unroll
        for (int i = 0; i < 4; i++) {
            xv[i] = *reinterpret_cast<const float4*>(xb + 4 * i);
            xv[i].x += nud; xv[i].y += nud; xv[i].z += nud; xv[i].w += nud;
        }
        double sq = 0.0;
        #pragma unroll
        for (int i = 0; i < 4; i++) {
            sq += (double)xv[i].x * xv[i].x; sq += (double)xv[i].y * xv[i].y;
            sq += (double)xv[i].z * xv[i].z; sq += (double)xv[i].w * xv[i].w;
        }
        sq += __shfl_xor_sync(0xFFFFFFFFu, sq, 1);
        sq += __shfl_xor_sync(0xFFFFFFFFu, sq, 2);
        sq += __shfl_xor_sync(0xFFFFFFFFu, sq, 4);
        float nf = fmaxf((float)sqrt(sq), 1e-6f);
        #pragma unroll
        for (int i = 0; i < 4; i++) {
            float a0 = xv[i].x / nf, a1 = xv[i].y / nf;    // IEEE fp32 div
            float a2 = xv[i].z / nf, a3 = xv[i].w / nf;
            __half2 h01 = __floats2half2_rn(a0, a1);
            __half2 h23 = __floats2half2_rn(a2, a3);
            uint2 st;
            st.x = *reinterpret_cast<uint32_t*>(&h01);
            st.y = *reinterpret_cast<uint32_t*>(&h23);
            *reinterpret_cast<uint2*>(&As[r * AS_LD + q * 16 + 4 * i]) = st;
        }
    }

    // ---------------- GEMM1 + fused softmax, 8 chunks of 64 codes ----------------
    for (int nt = 0; nt < 8; nt++) {
        CP_WAIT0();
        __syncthreads();    // Bs(nt) ready; Cbuf free (fused(nt-1) done)

        {   // 16 warps -> 4x4 grid of 32x16 tiles over [128 rows x 64 codes]
            wmma::fragment<wmma::matrix_a, 16, 16, 16, __half, wmma::row_major> af[2];
            wmma::fragment<wmma::matrix_b, 16, 16, 16, __half, wmma::col_major> bf;
            wmma::fragment<wmma::accumulator, 16, 16, 16, float> ac[2];
            #pragma unroll
            for (int i = 0; i < 2; i++) wmma::fill_fragment(ac[i], 0.0f);
            #pragma unroll
            for (int k0 = 0; k0 < 8; k0++) {
                #pragma unroll
                for (int i = 0; i < 2; i++)
                    wmma::load_matrix_sync(af[i], As + (rg * 32 + i * 16) * AS_LD + k0 * 16, AS_LD);
                wmma::load_matrix_sync(bf, Bs + (cg * 16) * AS_LD + k0 * 16, AS_LD);
                #pragma unroll
                for (int i = 0; i < 2; i++)
                    wmma::mma_sync(ac[i], af[i], bf, ac[i]);
            }
            #pragma unroll
            for (int i = 0; i < 2; i++)
                wmma::store_matrix_sync(Cbuf + (rg * 32 + i * 16) * C1_LD + cg * 16,
                                        ac[i], C1_LD, wmma::mem_row_major);
        }
        __syncthreads();    // Cbuf visible; Bs consumed

        if (nt < 7) {       // stage next B; fused pass hides the copy
            #pragma unroll
            for (int i = 0; i < 2; i++) {
                int idx = t + THREADS * i;
                int r = idx >> 4, c = idx & 15;
                cp_async16(&Bs[r * AS_LD + c * 8],
                           &g_cf16[(size_t)((nt + 1) * 64 + r) * 128 + c * 8]);
            }
            CP_COMMIT();
        }

        // fused pass: warp w owns rows 8w..8w+7; lane owns 2 consecutive codes
        float2 nz[8];
        #pragma unroll
        for (int i = 0; i < 8; i++)
            nz[i] = *reinterpret_cast<const float2*>(
                &noise[(size_t)(row0 + w * 8 + i) * NC + nt * 64 + 2 * lane]);

        #pragma unroll
        for (int rr8 = 0; rr8 < 8; rr8++) {
            int rr = w * 8 + rr8;
            float2 ab2 = *reinterpret_cast<const float2*>(&Cbuf[rr * C1_LD + 2 * lane]);
            float v0 = 2.0f * ab2.x + nz[rr8].x;
            float v1 = 2.0f * ab2.y + nz[rr8].y;
            float mc = fmaxf(v0, v1);
            float lm1, lm2;
            int li;
            if (ab2.x >= ab2.y) { lm1 = ab2.x; lm2 = ab2.y; li = nt * 64 + 2 * lane; }
            else                { lm1 = ab2.y; lm2 = ab2.x; li = nt * 64 + 2 * lane + 1; }
            {   // ab f16 copy for tier-2 candidate filter
                __half2 a01 = __floats2half2_rn(ab2.x, ab2.y);
                AB32[(size_t)(row0 + rr) * 256 + nt * 32 + lane] =
                    *reinterpret_cast<uint32_t*>(&a01);
            }
            #pragma unroll
            for (int d2 = 1; d2 <= 16; d2 <<= 1) {
                mc = fmaxf(mc, __shfl_xor_sync(0xFFFFFFFFu, mc, d2));
                float om1 = __shfl_xor_sync(0xFFFFFFFFu, lm1, d2);
                float om2 = __shfl_xor_sync(0xFFFFFFFFu, lm2, d2);
                int   oi  = __shfl_xor_sync(0xFFFFFFFFu, li,  d2);
                if (om1 > lm1)       { lm2 = fmaxf(lm1, om2); lm1 = om1; li = oi; }
                else if (om1 == lm1) { lm2 = lm1; li = min(li, oi); }
                else                 { lm2 = fmaxf(lm2, om1); }
            }
            float e0 = __expf(v0 - mc), e1 = __expf(v1 - mc);
            {
                __half2 h01 = __floats2half2_rn(e0, e1);
                EU32[(size_t)(row0 + rr) * 256 + nt * 32 + lane] =
                    *reinterpret_cast<uint32_t*>(&h01);
            }
            float sum = e0 + e1;
            #pragma unroll
            for (int d2 = 1; d2 <= 16; d2 <<= 1)
                sum += __shfl_xor_sync(0xFFFFFFFFu, sum, d2);
            if (lane == 0) {
                float gm1 = s_m1[rr], gm2 = s_m2[rr];
                int gi = s_i1[rr];
                if (lm1 > gm1)       { gm2 = fmaxf(gm1, lm2); gm1 = lm1; gi = li; }
                else if (lm1 == gm1) { gm2 = gm1; gi = min(gi, li); }
                else                 { gm2 = fmaxf(gm2, lm1); }
                s_m1[rr] = gm1; s_m2[rr] = gm2; s_i1[rr] = gi;
                s_mc[nt][rr] = mc;
                s_sc[nt][rr] = sum;
            }
        }
    }
    __syncthreads();

    // ---------------- finalize per row ----------------
    if (t < R_TILE) {
        float m = -CUDART_INF_F;
        #pragma unroll
        for (int c = 0; c < 8; c++) m = fmaxf(m, s_mc[c][t]);
        float wgt[8], s = 0.f;
        #pragma unroll
        for (int c = 0; c < 8; c++) {
            wgt[c] = __expf(s_mc[c][t] - m);
            s += s_sc[c][t] * wgt[c];
        }
        float inv = 1.0f / s;
        #pragma unroll
        for (int c = 0; c < 8; c++) s_ci[c][t] = wgt[c] * inv;
        if (s_m1[t] - s_m2[t] > MARGIN) out_i[row0 + t] = (float)s_i1[t];
        else { int p = atomicAdd(&s_cnt, 1); s_flag[p] = t; }
    }
    __syncthreads();

    // preload GEMM2 chunk 0 (codebook k-rows 0..63 -> Bs, eu chunk 0 -> EUa);
    // tier-2 hides the latency.
    #pragma unroll
    for (int i = 0; i < 2; i++) {
        int idx = t + THREADS * i;
        int rb = idx >> 4, cb = idx & 15;
        cp_async16(&Bs[rb * AS_LD + cb * 8], &g_cf16[(size_t)rb * 128 + cb * 8]);
        int re = idx >> 3, ce = idx & 7;
        cp_async16(&EUa[re * EU_LD + ce * 8], &g_eu[(size_t)(row0 + re) * NC + ce * 8]);
    }
    CP_COMMIT();

    // ---------------- tier-2: warp-parallel exact reference argmin ----------------
    {
        int cnt = s_cnt;
        for (int f = w; f < cnt; f += 16) {
            int rr = s_flag[f];
            int grr = row0 + rr;
            float nud = (1.0f - mask[grr]) * 1e-6f;
            float4 xv = *reinterpret_cast<const float4*>(&x[(size_t)grr * D + 4 * lane]);
            xv.x += nud; xv.y += nud; xv.z += nud; xv.w += nud;
            double sq = (double)xv.x * xv.x + (double)xv.y * xv.y +
                        (double)xv.z * xv.z + (double)xv.w * xv.w;
            #pragma unroll
            for (int d2 = 1; d2 <= 16; d2 <<= 1)
                sq += __shfl_xor_sync(0xFFFFFFFFu, sq, d2);
            float nf = fmaxf((float)sqrt(sq), 1e-6f);
            s_xw[w][4 * lane + 0] = xv.x / nf;
            s_xw[w][4 * lane + 1] = xv.y / nf;
            s_xw[w][4 * lane + 2] = xv.z / nf;
            s_xw[w][4 * lane + 3] = xv.w / nf;
            __syncwarp();
            float m1r = s_m1[rr];
            float bd = CUDART_INF_F;
            int bi = 1 << 30;
            #pragma unroll
            for (int j = 0; j < 16; j++) {
                int code = j * 32 + lane;
                float abf = __half2float(g_ab[(size_t)grr * NC + code]);
                if (abf >= m1r - CAND_MARGIN) {
                    const float* cj = codebook + (size_t)code * D;
                    float acc = 0.0f;
                    #pragma unroll 8
                    for (int k = 0; k < 128; k++)
                        acc = fmaf(s_xw[w][k], cj[k], acc);   // serial ascending k (matches ref)
                    float df = (1.0f - 2.0f * acc) + 1.0f;
                    if (df < bd || (df == bd && code < bi)) { bd = df; bi = code; }
                }
            }
            #pragma unroll
            for (int d2 = 1; d2 <= 16; d2 <<= 1) {
                float od = __shfl_xor_sync(0xFFFFFFFFu, bd, d2);
                int   oi = __shfl_xor_sync(0xFFFFFFFFu, bi, d2);
                if (od < bd || (od == bd && oi < bi)) { bd = od; bi = oi; }
            }
            if (lane == 0) out_i[grr] = (float)bi;
            __syncwarp();
        }
    }

    // ---------------- GEMM2: quantized = e @ C, 8 K-chunks of 64 ----------------
    wmma::fragment<wmma::accumulator, 16, 16, 16, float> ac2[2][2];
    #pragma unroll
    for (int i = 0; i < 2; i++)
        #pragma unroll
        for (int j = 0; j < 2; j++) wmma::fill_fragment(ac2[i][j], 0.0f);

    for (int kc = 0; kc < 8; kc++) {
        __half* Ecur  = (kc & 1) ? EUb : EUa;
        __half* Enext = (kc & 1) ? EUa : EUb;
        CP_WAIT0();
        __syncthreads();    // EU(kc) + Bs(kc) ready; As free (MMA(kc-1) done)

        if (kc < 7) {       // stage next eu chunk now; convert hides it
            #pragma unroll
            for (int i = 0; i < 2; i++) {
                int idx = t + THREADS * i;
                int re = idx >> 3, ce = idx & 7;
                cp_async16(&Enext[re * EU_LD + ce * 8],
                           &g_eu[(size_t)(row0 + re) * NC + (kc + 1) * 64 + ce * 8]);
            }
            CP_COMMIT();
        }

        // convert: scale raw eu from smem, emit out_e (f32), stage As (f16)
        {
            int r = t >> 2, q = t & 3;    // 4 threads per row, 16 halves each
            float ci = s_ci[kc][r];
            #pragma unroll
            for (int i = 0; i < 4; i++) {
                uint2 pk = *reinterpret_cast<const uint2*>(&Ecur[r * EU_LD + q * 16 + 4 * i]);
                __half2 h0 = *reinterpret_cast<__half2*>(&pk.x);
                __half2 h1 = *reinterpret_cast<__half2*>(&pk.y);
                float4 e4;
                e4.x = __half2float(h0.x) * ci; e4.y = __half2float(h0.y) * ci;
                e4.z = __half2float(h1.x) * ci; e4.w = __half2float(h1.y) * ci;
                *reinterpret_cast<float4*>(
                    &out_e[(size_t)(row0 + r) * NC + kc * 64 + q * 16 + 4 * i]) = e4;
                __half2 o0 = __floats2half2_rn(e4.x, e4.y);
                __half2 o1 = __floats2half2_rn(e4.z, e4.w);
                uint2 st;
                st.x = *reinterpret_cast<uint32_t*>(&o0);
                st.y = *reinterpret_cast<uint32_t*>(&o1);
                *reinterpret_cast<uint2*>(&As[r * AS_LD + q * 16 + 4 * i]) = st;
            }
        }
        __syncthreads();    // As ready

        {   // 16 warps -> 4x4 grid of 32x32 tiles, k = 64
            wmma::fragment<wmma::matrix_a, 16, 16, 16, __half, wmma::row_major> af[2];
            wmma::fragment<wmma::matrix_b, 16, 16, 16, __half, wmma::row_major> bf[2];
            #pragma unroll
            for (int k0 = 0; k0 < 4; k0++) {
                #pragma unroll
                for (int i = 0; i < 2; i++)
                    wmma::load_matrix_sync(af[i], As + (rg * 32 + i * 16) * AS_LD + k0 * 16, AS_LD);
                #pragma unroll
                for (int j = 0; j < 2; j++)
                    wmma::load_matrix_sync(bf[j], Bs + (k0 * 16) * AS_LD + cg * 32 + j * 16, AS_LD);
                #pragma unroll
                for (int i = 0; i < 2; i++)
                    #pragma unroll
                    for (int j = 0; j < 2; j++)
                        wmma::mma_sync(ac2[i][j], af[i], bf[j], ac2[i][j]);
            }
        }
        __syncthreads();    // Bs consumed

        if (kc < 7) {       // stage next codebook k-chunk
            #pragma unroll
            for (int i = 0; i < 2; i++) {
                int idx = t + THREADS * i;
                int rb = idx >> 4, cb = idx & 15;
                cp_async16(&Bs[rb * AS_LD + cb * 8],
                           &g_cf16[(size_t)((kc + 1) * 64 + rb) * 128 + cb * 8]);
            }
            CP_COMMIT();
        }
    }

    // epilogue in two 64-row halves through the (now-dead) EU region
    {
        float* Cq = reinterpret_cast<float*>(region);
        #pragma unroll
        for (int h = 0; h < 2; h++) {
            if ((rg >> 1) == h) {
                #pragma unroll
                for (int i = 0; i < 2; i++)
                    #pragma unroll
                    for (int j = 0; j < 2; j++)
                        wmma::store_matrix_sync(
                            Cq + ((rg & 1) * 32 + i * 16) * C2_LD + cg * 32 + j * 16,
                            ac2[i][j], C2_LD, wmma::mem_row_major);
            }
            __syncthreads();
            int r = t >> 3, q = t & 7;
            #pragma unroll
            for (int i = 0; i < 2; i++) {
                int c = q * 16 + i * 8;
                float4 o0 = *reinterpret_cast<float4*>(&Cq[r * C2_LD + c]);
                float4 o1 = *reinterpret_cast<float4*>(&Cq[r * C2_LD + c + 4]);
                *reinterpret_cast<float4*>(out_q + (size_t)(row0 + h * 64 + r) * D + c) = o0;
                *reinterpret_cast<float4*>(out_q + (size_t)(row0 + h * 64 + r) * D + c + 4) = o1;
            }
            __syncthreads();
        }
    }
}

extern "C" void kernel_launch(void* const* d_in, const int* in_sizes, int n_in,
                              void* d_out, int out_size) {
    const float* x        = (const float*)d_in[0];
    const float* mask     = (const float*)d_in[1];
    const float* codebook = (const float*)d_in[2];
    const float* noise    = (const float*)d_in[3];

    float* out   = (float*)d_out;
    float* out_q = out;
    float* out_e = out + (size_t)NROWS * D;
    float* out_i = out_e + (size_t)NROWS * NC;

    cudaFuncSetAttribute(k2_main, cudaFuncAttributeMaxDynamicSharedMemorySize, DYN_BYTES);

    k0_prep<<<(NC * D + 255) / 256, 256>>>(codebook);
    k2_main<<<NROWS / R_TILE, THREADS, DYN_BYTES>>>(x, mask, codebook, noise,
                                                    out_q, out_e, out_i);
}